// round 14
// baseline (speedup 1.0000x reference)
#include <cuda_runtime.h>
#include <cuda_bf16.h>
#include <cuda_fp16.h>
#include <math.h>
#include <stdint.h>

#define NT 64
#define NQ 256
#define NPK 100000
#define NE 262144
#define NN 16384
#define DS 64
#define DV 32
#define TEH 128
#define FF 160

#define TILE_E 64
#define TILES4 4096          // tiles per scale (NE / 64)
#define BPS 222              // blocks per scale (444 total -> 3 CTAs/SM)
#define WSTR 97              // Hh row stride (32-bit words, odd)
#define ASTR 37              // A row stride (32-bit words)
#define NTHREADS 256

// smem byte offsets (54784 B total -> 3 CTAs/SM)
// Hh (fp16 H slab) overlaps the prologue-only B-fragment staging.
#define OFF_A    0           // 2 x 64 x 37 words = 18944
#define OFF_HH   18944       // 64 x 97 words = 24832 (prologue: Bf 24576)
#define OFF_RBS  43776       // 2 x 64 x 9 floats = 4608
#define OFF_DIRS 48384       // 2 x 768 = 1536
#define OFF_INVS 49920       // 512
#define OFF_SRCS 50432       // 512
#define OFF_DSTS 50944       // 512
#define OFF_TTS  51456       // 512
#define OFF_W1S  51968       // 2048
#define OFF_B2S  54016       // 768
#define EDGE_SMEM 54784

__device__ float g_kfeat[NN * FF];
__device__ int   g_cnt[2 * NN];
__device__ int   g_cur[2 * NN];
__device__ float g_invcnt[2 * NN];
__device__ float g_qx[NN * 3];
__device__ float g_R[NT * 9];
__device__ float g_pre[2 * NT * 64];
__device__ int2  g_srt[2 * NE];

__device__ __forceinline__ uint32_t pack_half2(float a, float b) {
    __half2 h = __floats2half2_rn(a, b);
    return *reinterpret_cast<uint32_t*>(&h);
}
__device__ __forceinline__ float2 unpack_half2(uint32_t w) {
    __half2 h = *reinterpret_cast<__half2*>(&w);
    return __half22float2(h);
}

#define MMA_F16(c, a, b) \
    asm volatile("mma.sync.aligned.m16n8k16.row.col.f32.f16.f16.f32 " \
        "{%0,%1,%2,%3}, {%4,%5,%6,%7}, {%8,%9}, {%0,%1,%2,%3};" \
        : "+f"((c)[0]), "+f"((c)[1]), "+f"((c)[2]), "+f"((c)[3]) \
        : "r"((a)[0]), "r"((a)[1]), "r"((a)[2]), "r"((a)[3]), \
          "r"((b)[0]), "r"((b)[1]))

// ---------------- small kernels ----------------
__global__ void zero_kernel(float* __restrict__ out) {
    int i = blockIdx.x * blockDim.x + threadIdx.x;
    int st = gridDim.x * blockDim.x;
    for (int z = i; z < NN * FF; z += st) g_kfeat[z] = 0.0f;
    for (int z = i; z < 2 * NN; z += st) g_cnt[z] = 0;
    if (i < 2 * NT * 3) out[i] = 0.0f;
}

__global__ void hist_kernel(const int* __restrict__ ed0, const int* __restrict__ ed1) {
    int i = blockIdx.x * blockDim.x + threadIdx.x;
    int st = gridDim.x * blockDim.x;
    for (int e = i; e < NE; e += st) atomicAdd(&g_cnt[ed0[e]], 1);
    for (int e = i; e < NE; e += st) atomicAdd(&g_cnt[NN + ed1[e]], 1);
}

__global__ void scan_kernel() {
    __shared__ int sm[1024];
    int tid = threadIdx.x;
    int base = tid * 32;
    int loc[32];
    int s = 0;
    #pragma unroll
    for (int i = 0; i < 32; i++) { loc[i] = g_cnt[base + i]; s += loc[i]; }
    sm[tid] = s;
    __syncthreads();
    for (int off = 1; off < 1024; off <<= 1) {
        int v = (tid >= off) ? sm[tid - off] : 0;
        __syncthreads();
        sm[tid] += v;
        __syncthreads();
    }
    int ex = sm[tid] - s;
    #pragma unroll
    for (int i = 0; i < 32; i++) { g_cur[base + i] = ex; ex += loc[i]; }
}

__global__ void scatter_kernel(const int* __restrict__ es0, const int* __restrict__ ed0,
                               const int* __restrict__ es1, const int* __restrict__ ed1) {
    int i = blockIdx.x * blockDim.x + threadIdx.x;
    int st = gridDim.x * blockDim.x;
    for (int e = i; e < NE; e += st) {
        int d = ed0[e];
        int pos = atomicAdd(&g_cur[d], 1);
        g_srt[pos] = make_int2(es0[e], d);
    }
    for (int e = i; e < NE; e += st) {
        int d = ed1[e];
        int pos = atomicAdd(&g_cur[NN + d], 1);
        g_srt[pos] = make_int2(es1[e], d);
    }
}

__global__ void prep_kernel(const float* __restrict__ Ts, const float* __restrict__ time_,
                            const float* __restrict__ query_x,
                            const float* __restrict__ W_qt, const float* __restrict__ b_qt,
                            const float* __restrict__ W1_r, const float* __restrict__ b1_r) {
    __shared__ float te[128];
    __shared__ float qemb[128];
    __shared__ float Rsh[9];
    __shared__ float tsh[3];
    int t = blockIdx.x;
    int tid = threadIdx.x;  // 128 threads
    float tv = time_[t];
    {
        int k = tid & 63;
        float f = __expf(-logf(10000.0f) * (float)k / 63.0f);
        float a = tv * f;
        te[tid] = (tid < 64) ? sinf(a) : cosf(a);
    }
    if (tid == 0) {
        float qw = Ts[t * 7 + 0], qa = Ts[t * 7 + 1], qb = Ts[t * 7 + 2], qc = Ts[t * 7 + 3];
        float nrm = rsqrtf(qw * qw + qa * qa + qb * qb + qc * qc);
        qw *= nrm; qa *= nrm; qb *= nrm; qc *= nrm;
        Rsh[0] = 1.0f - 2.0f * (qb * qb + qc * qc);
        Rsh[1] = 2.0f * (qa * qb - qw * qc);
        Rsh[2] = 2.0f * (qa * qc + qw * qb);
        Rsh[3] = 2.0f * (qa * qb + qw * qc);
        Rsh[4] = 1.0f - 2.0f * (qa * qa + qc * qc);
        Rsh[5] = 2.0f * (qb * qc - qw * qa);
        Rsh[6] = 2.0f * (qa * qc - qw * qb);
        Rsh[7] = 2.0f * (qb * qc + qw * qa);
        Rsh[8] = 1.0f - 2.0f * (qa * qa + qb * qb);
        tsh[0] = Ts[t * 7 + 4]; tsh[1] = Ts[t * 7 + 5]; tsh[2] = Ts[t * 7 + 6];
        #pragma unroll
        for (int i = 0; i < 9; i++) g_R[t * 9 + i] = Rsh[i];
    }
    __syncthreads();
    {
        int o = tid;
        float acc = b_qt[o];
        for (int k = 0; k < 128; k++) acc += te[k] * W_qt[k * TEH + o];
        qemb[o] = acc;
    }
    __syncthreads();
    {
        int s = tid >> 6, j = tid & 63;
        float acc = b1_r[s * 64 + j];
        const float* w = W1_r + s * 136 * 64 + 8 * 64 + j;
        for (int i = 0; i < 128; i++) acc += qemb[i] * w[i * 64];
        g_pre[(s * NT + t) * 64 + j] = acc;
    }
    for (int q = tid; q < NQ; q += blockDim.x) {
        float x = query_x[q * 3 + 0], y = query_x[q * 3 + 1], z = query_x[q * 3 + 2];
        int n = t * NQ + q;
        g_qx[n * 3 + 0] = Rsh[0] * x + Rsh[1] * y + Rsh[2] * z + tsh[0];
        g_qx[n * 3 + 1] = Rsh[3] * x + Rsh[4] * y + Rsh[5] * z + tsh[1];
        g_qx[n * 3 + 2] = Rsh[6] * x + Rsh[7] * y + Rsh[8] * z + tsh[2];
    }
    int gtid = t * blockDim.x + tid;
    int gst = gridDim.x * blockDim.x;
    for (int z = gtid; z < 2 * NN; z += gst)
        g_invcnt[z] = 1.0f / ((float)g_cnt[z] + 1e-8f);
}

// ---------------- fused edge kernel: fp16 mma, 3 CTAs/SM ----------------
// 444 blocks of 256 threads (3 per SM); even blocks scale 0, odd scale 1;
// 64-edge tiles. H stored as fp16 (half2 words, WSTR stride) to fit 3 CTAs;
// epilogue fused into the GEMM loop (per-mc acc of 12 regs) to fit the
// 84-register cap. Two barriers/tile; scatter overlaps next tile's A+C.
__global__ __launch_bounds__(NTHREADS, 3)
void edge_mma_kernel(
    const float* __restrict__ kx0, const float* __restrict__ kf0,
    const float* __restrict__ kx1, const float* __restrict__ kf1,
    const float* __restrict__ W1_r, const float* __restrict__ W2_r,
    const float* __restrict__ b2_r) {
    extern __shared__ char smem[];
    int tid = threadIdx.x;
    int wid = tid >> 5, lane = tid & 31;
    int quad = lane >> 2, lm4 = lane & 3;
    int s = blockIdx.x & 1;
    int tstart = blockIdx.x >> 1;

    const float* kx = s ? kx1 : kx0;
    const float* kf = s ? kf1 : kf0;
    const float* preS = g_pre + s * NT * 64;
    const float* icS = g_invcnt + s * NN;
    const int2* srtS = g_srt + s * NE;

    uint32_t* AwB = (uint32_t*)(smem + OFF_A);        // 2 buffers of 64*ASTR
    uint2*  Bf2  = (uint2*)(smem + OFF_HH);           // prologue-only staging
    uint32_t* Hh = (uint32_t*)(smem + OFF_HH);        // fp16 H slab (half2 words)
    float* rbsB  = (float*)(smem + OFF_RBS);
    float* dirsB = (float*)(smem + OFF_DIRS);
    float* invsB = (float*)(smem + OFF_INVS);
    int*   srcsB = (int*)(smem + OFF_SRCS);
    int*   dstsB = (int*)(smem + OFF_DSTS);
    int*   ttsB  = (int*)(smem + OFF_TTS);
    float* W1s  = (float*)(smem + OFF_W1S);
    float* b2s  = (float*)(smem + OFF_B2S);

    // --- prologue: W1, b2, B-fragment pack (fp16) ---
    for (int i = tid; i < 512; i += NTHREADS) W1s[i] = W1_r[s * (136 * 64) + i];
    for (int i = tid; i < 192; i += NTHREADS) b2s[i] = b2_r[s * 192 + i];
    for (int idx = tid; idx < 3072; idx += NTHREADS) {
        int l = idx & 31;
        int f = idx >> 5;
        int gn = f % 24;
        int kt = f / 24;
        int n = gn * 8 + (l >> 2);
        int k0 = kt * 16 + (l & 3) * 2;
        const float* w2 = W2_r + s * 12288;
        uint32_t r0 = pack_half2(w2[k0 * 192 + n], w2[(k0 + 1) * 192 + n]);
        uint32_t r1 = pack_half2(w2[(k0 + 8) * 192 + n], w2[(k0 + 9) * 192 + n]);
        Bf2[f * 32 + l] = make_uint2(r0, r1);
    }
    __syncthreads();

    int cg = wid;           // column group: cols [24cg, 24cg+24)

    // per-warp B fragments resident in registers (3 nt x 4 kt x 2 regs)
    uint32_t bfr[3][4][2];
    #pragma unroll
    for (int nt = 0; nt < 3; nt++)
        #pragma unroll
        for (int kt = 0; kt < 4; kt++) {
            int f = kt * 24 + (cg * 3 + nt);
            uint2 v = Bf2[f * 32 + lane];
            bfr[nt][kt][0] = v.x;
            bfr[nt][kt][1] = v.y;
        }
    __syncthreads();   // bfr copied before GEMM epilogue overwrites Bf2 region

    // --- initial phase 1 (direct) for the first tile into buffer 0 ---
    int buf = 0;
    if (tid < TILE_E && tstart < TILES4) {
        int2 sd = srtS[tstart * TILE_E + tid];
        int src = sd.x, dst = sd.y;
        float rx = kx[src * 3 + 0] - g_qx[dst * 3 + 0];
        float ry = kx[src * 3 + 1] - g_qx[dst * 3 + 1];
        float rz = kx[src * 3 + 2] - g_qx[dst * 3 + 2];
        float r = sqrtf(rx * rx + ry * ry + rz * rz);
        float ir = 1.0f / (r + 1e-8f);
        dirsB[tid * 3 + 0] = rx * ir;
        dirsB[tid * 3 + 1] = ry * ir;
        dirsB[tid * 3 + 2] = rz * ir;
        #pragma unroll
        for (int i = 0; i < 8; i++) {
            float dcl = r - (4.0f / 7.0f) * (float)i;
            rbsB[tid * 9 + i] = __expf(-dcl * dcl * 4.0f);
        }
        invsB[tid] = icS[dst];
        srcsB[tid] = src; dstsB[tid] = dst; ttsB[tid] = dst >> 8;
    }
    __syncthreads();

    for (int tile = tstart; tile < TILES4; tile += BPS) {
        int nxt = tile + BPS;
        int nbuf = buf ^ 1;
        float* rbs  = rbsB + buf * 576;
        float* dirs = dirsB + buf * 192;
        float* invs = invsB + buf * 64;
        int*   srcs = srcsB + buf * 64;
        int*   dsts = dstsB + buf * 64;
        int*   tts  = ttsB + buf * 64;
        uint32_t* Aw = AwB + buf * (64 * ASTR);

        // step A: issue loads for next tile's geometry (registers, consumed at step E)
        int nsrc = 0, ndst = 0;
        float nkx0 = 0.f, nkx1 = 0.f, nkx2 = 0.f;
        float nqx0 = 0.f, nqx1 = 0.f, nqx2 = 0.f, nic = 0.f;
        if (tid < TILE_E && nxt < TILES4) {
            int2 sd = __ldg(srtS + nxt * TILE_E + tid);
            nsrc = sd.x; ndst = sd.y;
            nkx0 = __ldg(kx + nsrc * 3 + 0);
            nkx1 = __ldg(kx + nsrc * 3 + 1);
            nkx2 = __ldg(kx + nsrc * 3 + 2);
            nqx0 = __ldg(g_qx + ndst * 3 + 0);
            nqx1 = __ldg(g_qx + ndst * 3 + 1);
            nqx2 = __ldg(g_qx + ndst * 3 + 2);
            nic = __ldg(icS + ndst);
        }

        // step C: phase 2 — layer1 + silu -> fp16 pairs into Aw[buf]
        {
            int row = tid & 63;
            int jr = (tid >> 6) * 16;
            float rb[8];
            #pragma unroll
            for (int i = 0; i < 8; i++) rb[i] = rbs[row * 9 + i];
            const float* prow = preS + tts[row] * 64;
            uint32_t hw[8];
            #pragma unroll
            for (int p = 0; p < 8; p++) {
                float av[2];
                #pragma unroll
                for (int q = 0; q < 2; q++) {
                    int j = jr + p * 2 + q;
                    float h = __ldg(prow + j);
                    #pragma unroll
                    for (int i = 0; i < 8; i++) h += rb[i] * W1s[i * 64 + j];
                    av[q] = h * (1.0f / (1.0f + __expf(-h)));
                }
                hw[p] = pack_half2(av[0], av[1]);
            }
            uint32_t base = row * ASTR + (jr >> 1);
            #pragma unroll
            for (int p = 0; p < 8; p++) Aw[base + p] = hw[p];
        }
        __syncthreads();   // postC: Aw[buf] ready; all warps finished prev scatter

        // step D: GEMM + fused fp16 epilogue. warp cg: cols [24cg,24cg+24).
        #pragma unroll
        for (int mc = 0; mc < 4; mc++) {
            int r0 = mc * 16 + quad;
            uint32_t ah[4][4];
            #pragma unroll
            for (int kt = 0; kt < 4; kt++) {
                uint32_t b0 = r0 * ASTR + kt * 8 + lm4;
                uint32_t b1 = (r0 + 8) * ASTR + kt * 8 + lm4;
                ah[kt][0] = Aw[b0];     ah[kt][1] = Aw[b1];
                ah[kt][2] = Aw[b0 + 4]; ah[kt][3] = Aw[b1 + 4];
            }
            #pragma unroll
            for (int nt = 0; nt < 3; nt++) {
                float acc[4] = {0.f, 0.f, 0.f, 0.f};
                #pragma unroll
                for (int kt = 0; kt < 4; kt++)
                    MMA_F16(acc, ah[kt], bfr[nt][kt]);
                int col = cg * 24 + nt * 8 + lm4 * 2;
                float bb0 = b2s[col], bb1 = b2s[col + 1];
                int c2 = (col >> 1);
                Hh[r0 * WSTR + c2] = pack_half2(acc[0] + bb0, acc[1] + bb1);
                Hh[(r0 + 8) * WSTR + c2] = pack_half2(acc[2] + bb0, acc[3] + bb1);
            }
        }

        // step E: phase-1 compute for next tile (loads from step A now resolved)
        if (tid < TILE_E && nxt < TILES4) {
            float rx = nkx0 - nqx0;
            float ry = nkx1 - nqx1;
            float rz = nkx2 - nqx2;
            float r = sqrtf(rx * rx + ry * ry + rz * rz);
            float ir = 1.0f / (r + 1e-8f);
            float* ndirs = dirsB + nbuf * 192;
            float* nrbs  = rbsB + nbuf * 576;
            ndirs[tid * 3 + 0] = rx * ir;
            ndirs[tid * 3 + 1] = ry * ir;
            ndirs[tid * 3 + 2] = rz * ir;
            #pragma unroll
            for (int i = 0; i < 8; i++) {
                float dcl = r - (4.0f / 7.0f) * (float)i;
                nrbs[tid * 9 + i] = __expf(-dcl * dcl * 4.0f);
            }
            invsB[nbuf * 64 + tid] = nic;
            srcsB[nbuf * 64 + tid] = nsrc;
            dstsB[nbuf * 64 + tid] = ndst;
            ttsB[nbuf * 64 + tid] = ndst >> 8;
        }
        __syncthreads();   // postF: Hh ready; E done -> metadata[nbuf] ready

        // step G: phase 5 — branch-free kf gather, messages, run-merged atomics.
        // Overlaps the next iteration's steps A+C in other warps.
        {
            int tx = lane;
            int hw2 = tx >> 1;      // half2 word index within 32-col block
            int hsel = tx & 1;
            float kb0[8], kb1[8], kb2[8], kb3[8], kb4[8];
            #pragma unroll
            for (int e8 = 0; e8 < 8; e8++) {
                int r = wid * 8 + e8;
                const float* kfr = kf + (size_t)srcs[r] * FF;
                kb0[e8] = __ldg(kfr + tx);
                kb1[e8] = __ldg(kfr + 32 + tx);
                kb2[e8] = __ldg(kfr + 64 + 3 * tx + 0);
                kb3[e8] = __ldg(kfr + 64 + 3 * tx + 1);
                kb4[e8] = __ldg(kfr + 64 + 3 * tx + 2);
            }
            float a0 = 0.f, a1 = 0.f, a2 = 0.f, a3 = 0.f, a4 = 0.f;
            float curinv = 0.f;
            int cur = -1;
            #pragma unroll
            for (int e8 = 0; e8 < 8; e8++) {
                int r = wid * 8 + e8;
                const uint32_t* hr = Hh + r * WSTR + hw2;
                float2 f0 = unpack_half2(hr[0]);
                float2 f1 = unpack_half2(hr[16]);
                float2 f2 = unpack_half2(hr[32]);
                float2 f3 = unpack_half2(hr[48]);
                float2 f4 = unpack_half2(hr[64]);
                float2 f5 = unpack_half2(hr[80]);
                float w0 = hsel ? f0.y : f0.x;
                float w1 = hsel ? f1.y : f1.x;
                float w2 = hsel ? f2.y : f2.x;
                float w3 = hsel ? f3.y : f3.x;
                float w4 = hsel ? f4.y : f4.x;
                float w5 = hsel ? f5.y : f5.x;
                float ks1 = kb0[e8], ks2 = kb1[e8];
                float kvx = kb2[e8], kvy = kb3[e8], kvz = kb4[e8];
                float dx = dirs[r * 3 + 0], dy = dirs[r * 3 + 1], dz = dirs[r * 3 + 2];
                float dot = kvx * dx + kvy * dy + kvz * dz;
                float fs1 = w0 * ks1 + w4 * dot;
                float fs2 = w1 * ks2;
                float t1 = w3 * ks1;
                float fvx = w2 * kvx + t1 * dx + w5 * (kvy * dz - kvz * dy);
                float fvy = w2 * kvy + t1 * dy + w5 * (kvz * dx - kvx * dz);
                float fvz = w2 * kvz + t1 * dz + w5 * (kvx * dy - kvy * dx);
                int dst = dsts[r];
                if (dst != cur) {
                    if (cur >= 0) {
                        float* p = g_kfeat + (size_t)cur * FF;
                        atomicAdd(p + tx, a0 * curinv);
                        atomicAdd(p + 32 + tx, a1 * curinv);
                        atomicAdd(p + 64 + 3 * tx + 0, a2 * curinv);
                        atomicAdd(p + 64 + 3 * tx + 1, a3 * curinv);
                        atomicAdd(p + 64 + 3 * tx + 2, a4 * curinv);
                    }
                    cur = dst; curinv = invs[r];
                    a0 = fs1; a1 = fs2; a2 = fvx; a3 = fvy; a4 = fvz;
                } else {
                    a0 += fs1; a1 += fs2; a2 += fvx; a3 += fvy; a4 += fvz;
                }
            }
            if (cur >= 0) {
                float* p = g_kfeat + (size_t)cur * FF;
                atomicAdd(p + tx, a0 * curinv);
                atomicAdd(p + 32 + tx, a1 * curinv);
                atomicAdd(p + 64 + 3 * tx + 0, a2 * curinv);
                atomicAdd(p + 64 + 3 * tx + 1, a3 * curinv);
                atomicAdd(p + 64 + 3 * tx + 2, a4 * curinv);
            }
        }
        // no barrier here: next postC orders G against buffer reuse
        buf = nbuf;
    }
}

// ---------------- tensor-product heads + final reduction ----------------
__global__ __launch_bounds__(256) void tp_kernel(
    const float* __restrict__ query_f, const float* __restrict__ query_x,
    const float* __restrict__ query_w,
    const float* __restrict__ p00, const float* __restrict__ prest,
    const float* __restrict__ Ws_tp, const float* __restrict__ Wv_tp,
    float* __restrict__ out) {
    __shared__ float Wss[96 * 33];
    __shared__ float Wvs[96 * 32];
    __shared__ float s_sh[8][96];
    __shared__ float v_sh[8][96 * 3];
    __shared__ float accOut[6];
    int tid = threadIdx.x;
    int w = tid >> 5, c = tid & 31;
    int n = blockIdx.x * 8 + w;
    int t = n >> 8, q = n & 255;
    if (tid < 6) accOut[tid] = 0.0f;

    const float* kfr = g_kfeat + (size_t)n * FF;
    const float* qfr = query_f + (size_t)q * FF;
    float ks1 = kfr[c], ks2 = kfr[32 + c];
    float kvx = kfr[64 + 3 * c + 0], kvy = kfr[64 + 3 * c + 1], kvz = kfr[64 + 3 * c + 2];
    float qs1 = qfr[c], qs2 = qfr[32 + c];
    float qrx = qfr[64 + 3 * c + 0], qry = qfr[64 + 3 * c + 1], qrz = qfr[64 + 3 * c + 2];
    float R[9];
    #pragma unroll
    for (int i = 0; i < 9; i++) R[i] = __ldg(g_R + t * 9 + i);
    float qvx = R[0] * qrx + R[1] * qry + R[2] * qrz;
    float qvy = R[3] * qrx + R[4] * qry + R[5] * qrz;
    float qvz = R[6] * qrx + R[7] * qry + R[8] * qrz;

    float lin[3], ang[3];
    for (int head = 0; head < 2; head++) {
        __syncthreads();
        for (int i = tid; i < 96 * 33; i += 256) Wss[i] = Ws_tp[head * (96 * 33) + i];
        for (int i = tid; i < 96 * 32; i += 256) Wvs[i] = Wv_tp[head * (96 * 32) + i];
        __syncthreads();
        float p1 = __ldg(p00 + head * 64 + c);
        float p2 = __ldg(p00 + head * 64 + 32 + c);
        float pr0 = __ldg(prest + head * 128 + c);
        float pr1 = __ldg(prest + head * 128 + 32 + c);
        float pr2 = __ldg(prest + head * 128 + 64 + c);
        float pr3 = __ldg(prest + head * 128 + 96 + c);
        s_sh[w][c] = p1 * ks1 * qs1;
        s_sh[w][32 + c] = p2 * ks2 * qs2;
        s_sh[w][64 + c] = pr2 * (kvx * qvx + kvy * qvy + kvz * qvz);
        v_sh[w][3 * c + 0] = pr0 * kvx * qs1;
        v_sh[w][3 * c + 1] = pr0 * kvy * qs1;
        v_sh[w][3 * c + 2] = pr0 * kvz * qs1;
        v_sh[w][3 * (32 + c) + 0] = pr1 * ks1 * qvx;
        v_sh[w][3 * (32 + c) + 1] = pr1 * ks1 * qvy;
        v_sh[w][3 * (32 + c) + 2] = pr1 * ks1 * qvz;
        v_sh[w][3 * (64 + c) + 0] = pr3 * (kvy * qvz - kvz * qvy);
        v_sh[w][3 * (64 + c) + 1] = pr3 * (kvz * qvx - kvx * qvz);
        v_sh[w][3 * (64 + c) + 2] = pr3 * (kvx * qvy - kvy * qvx);
        __syncwarp();
        float sg = 0.0f, vmx = 0.0f, vmy = 0.0f, vmz = 0.0f;
        #pragma unroll 4
        for (int ch = 0; ch < 96; ch++) {
            float sv = s_sh[w][ch];
            sg += sv * Wss[ch * 33 + 1 + c];
            float wv = Wvs[ch * 32 + c];
            vmx += v_sh[w][3 * ch + 0] * wv;
            vmy += v_sh[w][3 * ch + 1] * wv;
            vmz += v_sh[w][3 * ch + 2] * wv;
        }
        float sig = 1.0f / (1.0f + __expf(-sg));
        float px = vmx * sig, py = vmy * sig, pz = vmz * sig;
        #pragma unroll
        for (int off = 16; off > 0; off >>= 1) {
            px += __shfl_xor_sync(0xffffffffu, px, off);
            py += __shfl_xor_sync(0xffffffffu, py, off);
            pz += __shfl_xor_sync(0xffffffffu, pz, off);
        }
        float sc = 1.0f / 32.0f;
        if (head == 0) { lin[0] = px * sc; lin[1] = py * sc; lin[2] = pz * sc; }
        else { ang[0] = px * sc; ang[1] = py * sc; ang[2] = pz * sc; }
        __syncwarp();
    }
    __syncthreads();
    if (c == 0) {
        float lwx = R[0] * lin[0] + R[3] * lin[1] + R[6] * lin[2];
        float lwy = R[1] * lin[0] + R[4] * lin[1] + R[7] * lin[2];
        float lwz = R[2] * lin[0] + R[5] * lin[1] + R[8] * lin[2];
        float awx = R[0] * ang[0] + R[3] * ang[1] + R[6] * ang[2];
        float awy = R[1] * ang[0] + R[4] * ang[1] + R[7] * ang[2];
        float awz = R[2] * ang[0] + R[5] * ang[1] + R[8] * ang[2];
        float qx0 = query_x[q * 3 + 0], qx1 = query_x[q * 3 + 1], qx2 = query_x[q * 3 + 2];
        float ox = qx1 * lwz - qx2 * lwy;
        float oy = qx2 * lwx - qx0 * lwz;
        float oz = qx0 * lwy - qx1 * lwx;
        float ww = query_w[q];
        atomicAdd(&accOut[0], ww * (ox + awx));
        atomicAdd(&accOut[1], ww * (oy + awy));
        atomicAdd(&accOut[2], ww * (oz + awz));
        atomicAdd(&accOut[3], ww * lwx);
        atomicAdd(&accOut[4], ww * lwy);
        atomicAdd(&accOut[5], ww * lwz);
    }
    __syncthreads();
    if (tid < 6) {
        int tt = blockIdx.x >> 5;
        int idx = (tid < 3) ? (tt * 3 + tid) : (NT * 3 + tt * 3 + (tid - 3));
        atomicAdd(out + idx, accOut[tid]);
    }
}

extern "C" void kernel_launch(void* const* d_in, const int* in_sizes, int n_in,
                              void* d_out, int out_size) {
    const float* Ts      = (const float*)d_in[0];
    const float* time_   = (const float*)d_in[1];
    const float* query_x = (const float*)d_in[2];
    const float* query_f = (const float*)d_in[3];
    const float* query_w = (const float*)d_in[4];
    const float* kx0     = (const float*)d_in[5];
    const float* kf0     = (const float*)d_in[6];
    const float* kx1     = (const float*)d_in[7];
    const float* kf1     = (const float*)d_in[8];
    const int*   es0     = (const int*)d_in[9];
    const int*   ed0     = (const int*)d_in[10];
    const int*   es1     = (const int*)d_in[11];
    const int*   ed1     = (const int*)d_in[12];
    const float* W_qt    = (const float*)d_in[13];
    const float* b_qt    = (const float*)d_in[14];
    const float* W1_r    = (const float*)d_in[15];
    const float* b1_r    = (const float*)d_in[16];
    const float* W2_r    = (const float*)d_in[17];
    const float* b2_r    = (const float*)d_in[18];
    const float* p00     = (const float*)d_in[19];
    const float* prest   = (const float*)d_in[20];
    const float* Ws_tp   = (const float*)d_in[21];
    const float* Wv_tp   = (const float*)d_in[22];
    float* out = (float*)d_out;

    cudaFuncSetAttribute(edge_mma_kernel, cudaFuncAttributeMaxDynamicSharedMemorySize,
                         EDGE_SMEM);

    zero_kernel<<<2048, 256>>>(out);
    hist_kernel<<<1024, 256>>>(ed0, ed1);
    scan_kernel<<<1, 1024>>>();
    prep_kernel<<<NT, 128>>>(Ts, time_, query_x, W_qt, b_qt, W1_r, b1_r);
    scatter_kernel<<<512, 256>>>(es0, ed0, es1, ed1);
    edge_mma_kernel<<<2 * BPS, NTHREADS, EDGE_SMEM>>>(kx0, kf0, kx1, kf1, W1_r, W2_r, b2_r);
    tp_kernel<<<NN / 8, 256>>>(query_f, query_x, query_w, p00, prest, Ws_tp, Wv_tp, out);
}

// round 15
// speedup vs baseline: 1.1002x; 1.1002x over previous
#include <cuda_runtime.h>
#include <cuda_bf16.h>
#include <cuda_fp16.h>
#include <math.h>
#include <stdint.h>

#define NT 64
#define NQ 256
#define NPK 100000
#define NE 262144
#define NN 16384
#define DS 64
#define DV 32
#define TEH 128
#define FF 160

#define TILE_E 64
#define TILES4 4096          // tiles per scale (NE / 64)
#define BPS 148              // blocks per scale (296 total)
#define HSTR 196             // Hs row stride (floats)
#define ASTR 36              // A row stride (32-bit words; 16B-aligned rows for ldmatrix)
#define NTHREADS 256

// smem byte offsets (79616 B total -> 2 CTAs/SM)
// Aw double-buffered; prologue B-fragment staging overlaps Hs.
#define OFF_A    0           // 2 x 64 x 36 words = 18432
#define OFF_HS   18432       // 64 x 196 floats = 50176 (prologue: Bf 24576)
#define OFF_RBS  68608       // 2 x 64 x 9 floats = 4608
#define OFF_DIRS 73216       // 2 x 768 = 1536
#define OFF_INVS 74752       // 512
#define OFF_SRCS 75264       // 512
#define OFF_DSTS 75776       // 512
#define OFF_TTS  76288       // 512
#define OFF_W1S  76800       // 2048
#define OFF_B2S  78848       // 768
#define EDGE_SMEM 79616

__device__ float g_kfeat[NN * FF];
__device__ int   g_cnt[2 * NN];
__device__ int   g_cur[2 * NN];
__device__ float g_invcnt[2 * NN];
__device__ float g_qx[NN * 3];
__device__ float g_R[NT * 9];
__device__ float g_pre[2 * NT * 64];
__device__ int2  g_srt[2 * NE];

__device__ __forceinline__ uint32_t pack_half2(float a, float b) {
    __half2 h = __floats2half2_rn(a, b);
    return *reinterpret_cast<uint32_t*>(&h);
}

#define MMA_F16(c, a, b) \
    asm volatile("mma.sync.aligned.m16n8k16.row.col.f32.f16.f16.f32 " \
        "{%0,%1,%2,%3}, {%4,%5,%6,%7}, {%8,%9}, {%0,%1,%2,%3};" \
        : "+f"((c)[0]), "+f"((c)[1]), "+f"((c)[2]), "+f"((c)[3]) \
        : "r"((a)[0]), "r"((a)[1]), "r"((a)[2]), "r"((a)[3]), \
          "r"((b)[0]), "r"((b)[1]))

#define LDSM_X4(r, addr) \
    asm volatile("ldmatrix.sync.aligned.m8n8.x4.shared.b16 {%0,%1,%2,%3}, [%4];" \
        : "=r"((r)[0]), "=r"((r)[1]), "=r"((r)[2]), "=r"((r)[3]) : "r"(addr))

// ---------------- small kernels ----------------
__global__ void zero_kernel(float* __restrict__ out) {
    int i = blockIdx.x * blockDim.x + threadIdx.x;
    int st = gridDim.x * blockDim.x;
    for (int z = i; z < NN * FF; z += st) g_kfeat[z] = 0.0f;
    for (int z = i; z < 2 * NN; z += st) g_cnt[z] = 0;
    if (i < 2 * NT * 3) out[i] = 0.0f;
}

__global__ void hist_kernel(const int* __restrict__ ed0, const int* __restrict__ ed1) {
    int i = blockIdx.x * blockDim.x + threadIdx.x;
    int st = gridDim.x * blockDim.x;
    for (int e = i; e < NE; e += st) atomicAdd(&g_cnt[ed0[e]], 1);
    for (int e = i; e < NE; e += st) atomicAdd(&g_cnt[NN + ed1[e]], 1);
}

__global__ void scan_kernel() {
    __shared__ int sm[1024];
    int tid = threadIdx.x;
    int base = tid * 32;
    int loc[32];
    int s = 0;
    #pragma unroll
    for (int i = 0; i < 32; i++) { loc[i] = g_cnt[base + i]; s += loc[i]; }
    sm[tid] = s;
    __syncthreads();
    for (int off = 1; off < 1024; off <<= 1) {
        int v = (tid >= off) ? sm[tid - off] : 0;
        __syncthreads();
        sm[tid] += v;
        __syncthreads();
    }
    int ex = sm[tid] - s;
    #pragma unroll
    for (int i = 0; i < 32; i++) { g_cur[base + i] = ex; ex += loc[i]; }
}

__global__ void scatter_kernel(const int* __restrict__ es0, const int* __restrict__ ed0,
                               const int* __restrict__ es1, const int* __restrict__ ed1) {
    int i = blockIdx.x * blockDim.x + threadIdx.x;
    int st = gridDim.x * blockDim.x;
    for (int e = i; e < NE; e += st) {
        int d = ed0[e];
        int pos = atomicAdd(&g_cur[d], 1);
        g_srt[pos] = make_int2(es0[e], d);
    }
    for (int e = i; e < NE; e += st) {
        int d = ed1[e];
        int pos = atomicAdd(&g_cur[NN + d], 1);
        g_srt[pos] = make_int2(es1[e], d);
    }
}

__global__ void prep_kernel(const float* __restrict__ Ts, const float* __restrict__ time_,
                            const float* __restrict__ query_x,
                            const float* __restrict__ W_qt, const float* __restrict__ b_qt,
                            const float* __restrict__ W1_r, const float* __restrict__ b1_r) {
    __shared__ float te[128];
    __shared__ float qemb[128];
    __shared__ float Rsh[9];
    __shared__ float tsh[3];
    int t = blockIdx.x;
    int tid = threadIdx.x;  // 128 threads
    float tv = time_[t];
    {
        int k = tid & 63;
        float f = __expf(-logf(10000.0f) * (float)k / 63.0f);
        float a = tv * f;
        te[tid] = (tid < 64) ? sinf(a) : cosf(a);
    }
    if (tid == 0) {
        float qw = Ts[t * 7 + 0], qa = Ts[t * 7 + 1], qb = Ts[t * 7 + 2], qc = Ts[t * 7 + 3];
        float nrm = rsqrtf(qw * qw + qa * qa + qb * qb + qc * qc);
        qw *= nrm; qa *= nrm; qb *= nrm; qc *= nrm;
        Rsh[0] = 1.0f - 2.0f * (qb * qb + qc * qc);
        Rsh[1] = 2.0f * (qa * qb - qw * qc);
        Rsh[2] = 2.0f * (qa * qc + qw * qb);
        Rsh[3] = 2.0f * (qa * qb + qw * qc);
        Rsh[4] = 1.0f - 2.0f * (qa * qa + qc * qc);
        Rsh[5] = 2.0f * (qb * qc - qw * qa);
        Rsh[6] = 2.0f * (qa * qc - qw * qb);
        Rsh[7] = 2.0f * (qb * qc + qw * qa);
        Rsh[8] = 1.0f - 2.0f * (qa * qa + qb * qb);
        tsh[0] = Ts[t * 7 + 4]; tsh[1] = Ts[t * 7 + 5]; tsh[2] = Ts[t * 7 + 6];
        #pragma unroll
        for (int i = 0; i < 9; i++) g_R[t * 9 + i] = Rsh[i];
    }
    __syncthreads();
    {
        int o = tid;
        float acc = b_qt[o];
        for (int k = 0; k < 128; k++) acc += te[k] * W_qt[k * TEH + o];
        qemb[o] = acc;
    }
    __syncthreads();
    {
        int s = tid >> 6, j = tid & 63;
        float acc = b1_r[s * 64 + j];
        const float* w = W1_r + s * 136 * 64 + 8 * 64 + j;
        for (int i = 0; i < 128; i++) acc += qemb[i] * w[i * 64];
        g_pre[(s * NT + t) * 64 + j] = acc;
    }
    for (int q = tid; q < NQ; q += blockDim.x) {
        float x = query_x[q * 3 + 0], y = query_x[q * 3 + 1], z = query_x[q * 3 + 2];
        int n = t * NQ + q;
        g_qx[n * 3 + 0] = Rsh[0] * x + Rsh[1] * y + Rsh[2] * z + tsh[0];
        g_qx[n * 3 + 1] = Rsh[3] * x + Rsh[4] * y + Rsh[5] * z + tsh[1];
        g_qx[n * 3 + 2] = Rsh[6] * x + Rsh[7] * y + Rsh[8] * z + tsh[2];
    }
    int gtid = t * blockDim.x + tid;
    int gst = gridDim.x * blockDim.x;
    for (int z = gtid; z < 2 * NN; z += gst)
        g_invcnt[z] = 1.0f / ((float)g_cnt[z] + 1e-8f);
}

// ---------------- fused edge kernel: fp16 mma, vectorized + ldmatrix ----------------
// 296 blocks of 256 threads (2 per SM); even blocks scale 0, odd scale 1;
// 64-edge tiles. R13 pipeline (2 barriers/tile, scatter overlaps next A+C);
// phase 2 uses float4 W1/pre loads + uint4 A stores; GEMM A-fragments loaded
// with ldmatrix.x4 (canonical m16n8k16 mapping, ASTR=36 words, conflict-free).
__global__ __launch_bounds__(NTHREADS, 2)
void edge_mma_kernel(
    const float* __restrict__ kx0, const float* __restrict__ kf0,
    const float* __restrict__ kx1, const float* __restrict__ kf1,
    const float* __restrict__ W1_r, const float* __restrict__ W2_r,
    const float* __restrict__ b2_r) {
    extern __shared__ char smem[];
    int tid = threadIdx.x;
    int wid = tid >> 5, lane = tid & 31;
    int quad = lane >> 2, lm4 = lane & 3;
    int s = blockIdx.x & 1;
    int tstart = blockIdx.x >> 1;

    const float* kx = s ? kx1 : kx0;
    const float* kf = s ? kf1 : kf0;
    const float* preS = g_pre + s * NT * 64;
    const float* icS = g_invcnt + s * NN;
    const int2* srtS = g_srt + s * NE;

    uint32_t* AwB = (uint32_t*)(smem + OFF_A);        // 2 buffers of 64*ASTR
    uint2*  Bf2  = (uint2*)(smem + OFF_HS);           // prologue-only staging
    float* Hs   = (float*)(smem + OFF_HS);
    float* rbsB  = (float*)(smem + OFF_RBS);
    float* dirsB = (float*)(smem + OFF_DIRS);
    float* invsB = (float*)(smem + OFF_INVS);
    int*   srcsB = (int*)(smem + OFF_SRCS);
    int*   dstsB = (int*)(smem + OFF_DSTS);
    int*   ttsB  = (int*)(smem + OFF_TTS);
    float* W1s  = (float*)(smem + OFF_W1S);
    float* b2s  = (float*)(smem + OFF_B2S);
    uint32_t aw_shared = (uint32_t)__cvta_generic_to_shared(AwB);

    // --- prologue: W1, b2, B-fragment pack (fp16) ---
    for (int i = tid; i < 512; i += NTHREADS) W1s[i] = W1_r[s * (136 * 64) + i];
    for (int i = tid; i < 192; i += NTHREADS) b2s[i] = b2_r[s * 192 + i];
    for (int idx = tid; idx < 3072; idx += NTHREADS) {
        int l = idx & 31;
        int f = idx >> 5;
        int gn = f % 24;
        int kt = f / 24;
        int n = gn * 8 + (l >> 2);
        int k0 = kt * 16 + (l & 3) * 2;
        const float* w2 = W2_r + s * 12288;
        uint32_t r0 = pack_half2(w2[k0 * 192 + n], w2[(k0 + 1) * 192 + n]);
        uint32_t r1 = pack_half2(w2[(k0 + 8) * 192 + n], w2[(k0 + 9) * 192 + n]);
        Bf2[f * 32 + l] = make_uint2(r0, r1);
    }
    __syncthreads();

    int cg = wid;           // column group: cols [24cg, 24cg+24)

    // per-warp B fragments resident in registers (3 nt x 4 kt x 2 regs)
    uint32_t bfr[3][4][2];
    #pragma unroll
    for (int nt = 0; nt < 3; nt++)
        #pragma unroll
        for (int kt = 0; kt < 4; kt++) {
            int f = kt * 24 + (cg * 3 + nt);
            uint2 v = Bf2[f * 32 + lane];
            bfr[nt][kt][0] = v.x;
            bfr[nt][kt][1] = v.y;
        }
    __syncthreads();   // bfr copied before Hs/phase4 overwrites Bf2 region

    // ldmatrix lane addressing (canonical m16n8k16 A-fragment mapping)
    int laneRow = ((lane >> 3) & 1) * 8 + (lane & 7);
    int laneColW = (lane >> 4) * 4;

    // --- initial phase 1 (direct) for the first tile into buffer 0 ---
    int buf = 0;
    if (tid < TILE_E && tstart < TILES4) {
        int2 sd = srtS[tstart * TILE_E + tid];
        int src = sd.x, dst = sd.y;
        float rx = kx[src * 3 + 0] - g_qx[dst * 3 + 0];
        float ry = kx[src * 3 + 1] - g_qx[dst * 3 + 1];
        float rz = kx[src * 3 + 2] - g_qx[dst * 3 + 2];
        float r = sqrtf(rx * rx + ry * ry + rz * rz);
        float ir = 1.0f / (r + 1e-8f);
        dirsB[tid * 3 + 0] = rx * ir;
        dirsB[tid * 3 + 1] = ry * ir;
        dirsB[tid * 3 + 2] = rz * ir;
        #pragma unroll
        for (int i = 0; i < 8; i++) {
            float dcl = r - (4.0f / 7.0f) * (float)i;
            rbsB[tid * 9 + i] = __expf(-dcl * dcl * 4.0f);
        }
        invsB[tid] = icS[dst];
        srcsB[tid] = src; dstsB[tid] = dst; ttsB[tid] = dst >> 8;
    }
    __syncthreads();

    for (int tile = tstart; tile < TILES4; tile += BPS) {
        int nxt = tile + BPS;
        int nbuf = buf ^ 1;
        float* rbs  = rbsB + buf * 576;
        float* dirs = dirsB + buf * 192;
        float* invs = invsB + buf * 64;
        int*   srcs = srcsB + buf * 64;
        int*   dsts = dstsB + buf * 64;
        int*   tts  = ttsB + buf * 64;
        uint32_t* Aw = AwB + buf * (64 * ASTR);
        uint32_t aw_s = aw_shared + buf * (64 * ASTR) * 4;

        // step A: issue loads for next tile's geometry (registers, consumed at step E)
        int nsrc = 0, ndst = 0;
        float nkx0 = 0.f, nkx1 = 0.f, nkx2 = 0.f;
        float nqx0 = 0.f, nqx1 = 0.f, nqx2 = 0.f, nic = 0.f;
        if (tid < TILE_E && nxt < TILES4) {
            int2 sd = __ldg(srtS + nxt * TILE_E + tid);
            nsrc = sd.x; ndst = sd.y;
            nkx0 = __ldg(kx + nsrc * 3 + 0);
            nkx1 = __ldg(kx + nsrc * 3 + 1);
            nkx2 = __ldg(kx + nsrc * 3 + 2);
            nqx0 = __ldg(g_qx + ndst * 3 + 0);
            nqx1 = __ldg(g_qx + ndst * 3 + 1);
            nqx2 = __ldg(g_qx + ndst * 3 + 2);
            nic = __ldg(icS + ndst);
        }

        // step C: phase 2 — layer1 + silu -> fp16 pairs into Aw[buf] (vectorized)
        {
            int row = tid & 63;
            int jr = (tid >> 6) * 16;
            float rb[8];
            #pragma unroll
            for (int i = 0; i < 8; i++) rb[i] = rbs[row * 9 + i];
            const float4* prow4 = (const float4*)(preS + tts[row] * 64 + jr);
            const float4* W14 = (const float4*)W1s;
            int wbase = jr >> 2;
            uint32_t hw[8];
            #pragma unroll
            for (int p = 0; p < 4; p++) {
                float4 h4 = __ldg(prow4 + p);
                float h0 = h4.x, h1 = h4.y, h2 = h4.z, h3 = h4.w;
                #pragma unroll
                for (int i = 0; i < 8; i++) {
                    float4 w = W14[i * 16 + wbase + p];
                    h0 += rb[i] * w.x; h1 += rb[i] * w.y;
                    h2 += rb[i] * w.z; h3 += rb[i] * w.w;
                }
                h0 *= 1.0f / (1.0f + __expf(-h0));
                h1 *= 1.0f / (1.0f + __expf(-h1));
                h2 *= 1.0f / (1.0f + __expf(-h2));
                h3 *= 1.0f / (1.0f + __expf(-h3));
                hw[p * 2] = pack_half2(h0, h1);
                hw[p * 2 + 1] = pack_half2(h2, h3);
            }
            uint4* dstp = (uint4*)(Aw + row * ASTR + (jr >> 1));
            dstp[0] = make_uint4(hw[0], hw[1], hw[2], hw[3]);
            dstp[1] = make_uint4(hw[4], hw[5], hw[6], hw[7]);
        }
        __syncthreads();   // postC: Aw[buf] ready; all warps finished prev scatter

        // step D: GEMM. warp cg: cols [24cg,24cg+24), rows 0..63. ldmatrix A.
        float acc[3][4][4];
        #pragma unroll
        for (int nt = 0; nt < 3; nt++)
            #pragma unroll
            for (int mc = 0; mc < 4; mc++)
                #pragma unroll
                for (int r = 0; r < 4; r++) acc[nt][mc][r] = 0.0f;

        #pragma unroll
        for (int mc = 0; mc < 4; mc++) {
            uint32_t ah[4][4];
            uint32_t rowAddr = aw_s + (((mc * 16 + laneRow) * ASTR) + laneColW) * 4;
            #pragma unroll
            for (int kt = 0; kt < 4; kt++)
                LDSM_X4(ah[kt], rowAddr + kt * 32);   // kt*8 words = 32 B
            #pragma unroll
            for (int nt = 0; nt < 3; nt++)
                #pragma unroll
                for (int kt = 0; kt < 4; kt++)
                    MMA_F16(acc[nt][mc], ah[kt], bfr[nt][kt]);
        }

        // step E: phase-1 compute for next tile (loads from step A now resolved)
        if (tid < TILE_E && nxt < TILES4) {
            float rx = nkx0 - nqx0;
            float ry = nkx1 - nqx1;
            float rz = nkx2 - nqx2;
            float r = sqrtf(rx * rx + ry * ry + rz * rz);
            float ir = 1.0f / (r + 1e-8f);
            float* ndirs = dirsB + nbuf * 192;
            float* nrbs  = rbsB + nbuf * 576;
            ndirs[tid * 3 + 0] = rx * ir;
            ndirs[tid * 3 + 1] = ry * ir;
            ndirs[tid * 3 + 2] = rz * ir;
            #pragma unroll
            for (int i = 0; i < 8; i++) {
                float dcl = r - (4.0f / 7.0f) * (float)i;
                nrbs[tid * 9 + i] = __expf(-dcl * dcl * 4.0f);
            }
            invsB[nbuf * 64 + tid] = nic;
            srcsB[nbuf * 64 + tid] = nsrc;
            dstsB[nbuf * 64 + tid] = ndst;
            ttsB[nbuf * 64 + tid] = ndst >> 8;
        }

        // step F: accumulators (+bias) -> Hs slab
        #pragma unroll
        for (int nt = 0; nt < 3; nt++) {
            int col = cg * 24 + nt * 8 + lm4 * 2;
            float bb0 = b2s[col], bb1 = b2s[col + 1];
            #pragma unroll
            for (int mc = 0; mc < 4; mc++) {
                int row = mc * 16 + quad;
                float2 v0 = make_float2(acc[nt][mc][0] + bb0, acc[nt][mc][1] + bb1);
                float2 v1 = make_float2(acc[nt][mc][2] + bb0, acc[nt][mc][3] + bb1);
                *(float2*)&Hs[row * HSTR + col] = v0;
                *(float2*)&Hs[(row + 8) * HSTR + col] = v1;
            }
        }
        __syncthreads();   // postF: Hs ready; E done -> metadata[nbuf] ready

        // step G: phase 5 — branch-free kf gather, messages, run-merged atomics.
        // Overlaps the next iteration's steps A+C in other warps.
        {
            int tx = lane;
            float kb0[8], kb1[8], kb2[8], kb3[8], kb4[8];
            #pragma unroll
            for (int e8 = 0; e8 < 8; e8++) {
                int r = wid * 8 + e8;
                const float* kfr = kf + (size_t)srcs[r] * FF;
                kb0[e8] = __ldg(kfr + tx);
                kb1[e8] = __ldg(kfr + 32 + tx);
                kb2[e8] = __ldg(kfr + 64 + 3 * tx + 0);
                kb3[e8] = __ldg(kfr + 64 + 3 * tx + 1);
                kb4[e8] = __ldg(kfr + 64 + 3 * tx + 2);
            }
            float a0 = 0.f, a1 = 0.f, a2 = 0.f, a3 = 0.f, a4 = 0.f;
            float curinv = 0.f;
            int cur = -1;
            #pragma unroll
            for (int e8 = 0; e8 < 8; e8++) {
                int r = wid * 8 + e8;
                float w0 = Hs[r * HSTR + tx];
                float w1 = Hs[r * HSTR + 32 + tx];
                float w2 = Hs[r * HSTR + 64 + tx];
                float w3 = Hs[r * HSTR + 96 + tx];
                float w4 = Hs[r * HSTR + 128 + tx];
                float w5 = Hs[r * HSTR + 160 + tx];
                float ks1 = kb0[e8], ks2 = kb1[e8];
                float kvx = kb2[e8], kvy = kb3[e8], kvz = kb4[e8];
                float dx = dirs[r * 3 + 0], dy = dirs[r * 3 + 1], dz = dirs[r * 3 + 2];
                float dot = kvx * dx + kvy * dy + kvz * dz;
                float fs1 = w0 * ks1 + w4 * dot;
                float fs2 = w1 * ks2;
                float t1 = w3 * ks1;
                float fvx = w2 * kvx + t1 * dx + w5 * (kvy * dz - kvz * dy);
                float fvy = w2 * kvy + t1 * dy + w5 * (kvz * dx - kvx * dz);
                float fvz = w2 * kvz + t1 * dz + w5 * (kvx * dy - kvy * dx);
                int dst = dsts[r];
                if (dst != cur) {
                    if (cur >= 0) {
                        float* p = g_kfeat + (size_t)cur * FF;
                        atomicAdd(p + tx, a0 * curinv);
                        atomicAdd(p + 32 + tx, a1 * curinv);
                        atomicAdd(p + 64 + 3 * tx + 0, a2 * curinv);
                        atomicAdd(p + 64 + 3 * tx + 1, a3 * curinv);
                        atomicAdd(p + 64 + 3 * tx + 2, a4 * curinv);
                    }
                    cur = dst; curinv = invs[r];
                    a0 = fs1; a1 = fs2; a2 = fvx; a3 = fvy; a4 = fvz;
                } else {
                    a0 += fs1; a1 += fs2; a2 += fvx; a3 += fvy; a4 += fvz;
                }
            }
            if (cur >= 0) {
                float* p = g_kfeat + (size_t)cur * FF;
                atomicAdd(p + tx, a0 * curinv);
                atomicAdd(p + 32 + tx, a1 * curinv);
                atomicAdd(p + 64 + 3 * tx + 0, a2 * curinv);
                atomicAdd(p + 64 + 3 * tx + 1, a3 * curinv);
                atomicAdd(p + 64 + 3 * tx + 2, a4 * curinv);
            }
        }
        // no barrier here: next postC orders G against buffer reuse
        buf = nbuf;
    }
}

// ---------------- tensor-product heads + final reduction ----------------
__global__ __launch_bounds__(256) void tp_kernel(
    const float* __restrict__ query_f, const float* __restrict__ query_x,
    const float* __restrict__ query_w,
    const float* __restrict__ p00, const float* __restrict__ prest,
    const float* __restrict__ Ws_tp, const float* __restrict__ Wv_tp,
    float* __restrict__ out) {
    __shared__ float Wss[96 * 33];
    __shared__ float Wvs[96 * 32];
    __shared__ float s_sh[8][96];
    __shared__ float v_sh[8][96 * 3];
    __shared__ float accOut[6];
    int tid = threadIdx.x;
    int w = tid >> 5, c = tid & 31;
    int n = blockIdx.x * 8 + w;
    int t = n >> 8, q = n & 255;
    if (tid < 6) accOut[tid] = 0.0f;

    const float* kfr = g_kfeat + (size_t)n * FF;
    const float* qfr = query_f + (size_t)q * FF;
    float ks1 = kfr[c], ks2 = kfr[32 + c];
    float kvx = kfr[64 + 3 * c + 0], kvy = kfr[64 + 3 * c + 1], kvz = kfr[64 + 3 * c + 2];
    float qs1 = qfr[c], qs2 = qfr[32 + c];
    float qrx = qfr[64 + 3 * c + 0], qry = qfr[64 + 3 * c + 1], qrz = qfr[64 + 3 * c + 2];
    float R[9];
    #pragma unroll
    for (int i = 0; i < 9; i++) R[i] = __ldg(g_R + t * 9 + i);
    float qvx = R[0] * qrx + R[1] * qry + R[2] * qrz;
    float qvy = R[3] * qrx + R[4] * qry + R[5] * qrz;
    float qvz = R[6] * qrx + R[7] * qry + R[8] * qrz;

    float lin[3], ang[3];
    for (int head = 0; head < 2; head++) {
        __syncthreads();
        for (int i = tid; i < 96 * 33; i += 256) Wss[i] = Ws_tp[head * (96 * 33) + i];
        for (int i = tid; i < 96 * 32; i += 256) Wvs[i] = Wv_tp[head * (96 * 32) + i];
        __syncthreads();
        float p1 = __ldg(p00 + head * 64 + c);
        float p2 = __ldg(p00 + head * 64 + 32 + c);
        float pr0 = __ldg(prest + head * 128 + c);
        float pr1 = __ldg(prest + head * 128 + 32 + c);
        float pr2 = __ldg(prest + head * 128 + 64 + c);
        float pr3 = __ldg(prest + head * 128 + 96 + c);
        s_sh[w][c] = p1 * ks1 * qs1;
        s_sh[w][32 + c] = p2 * ks2 * qs2;
        s_sh[w][64 + c] = pr2 * (kvx * qvx + kvy * qvy + kvz * qvz);
        v_sh[w][3 * c + 0] = pr0 * kvx * qs1;
        v_sh[w][3 * c + 1] = pr0 * kvy * qs1;
        v_sh[w][3 * c + 2] = pr0 * kvz * qs1;
        v_sh[w][3 * (32 + c) + 0] = pr1 * ks1 * qvx;
        v_sh[w][3 * (32 + c) + 1] = pr1 * ks1 * qvy;
        v_sh[w][3 * (32 + c) + 2] = pr1 * ks1 * qvz;
        v_sh[w][3 * (64 + c) + 0] = pr3 * (kvy * qvz - kvz * qvy);
        v_sh[w][3 * (64 + c) + 1] = pr3 * (kvz * qvx - kvx * qvz);
        v_sh[w][3 * (64 + c) + 2] = pr3 * (kvx * qvy - kvy * qvx);
        __syncwarp();
        float sg = 0.0f, vmx = 0.0f, vmy = 0.0f, vmz = 0.0f;
        #pragma unroll 4
        for (int ch = 0; ch < 96; ch++) {
            float sv = s_sh[w][ch];
            sg += sv * Wss[ch * 33 + 1 + c];
            float wv = Wvs[ch * 32 + c];
            vmx += v_sh[w][3 * ch + 0] * wv;
            vmy += v_sh[w][3 * ch + 1] * wv;
            vmz += v_sh[w][3 * ch + 2] * wv;
        }
        float sig = 1.0f / (1.0f + __expf(-sg));
        float px = vmx * sig, py = vmy * sig, pz = vmz * sig;
        #pragma unroll
        for (int off = 16; off > 0; off >>= 1) {
            px += __shfl_xor_sync(0xffffffffu, px, off);
            py += __shfl_xor_sync(0xffffffffu, py, off);
            pz += __shfl_xor_sync(0xffffffffu, pz, off);
        }
        float sc = 1.0f / 32.0f;
        if (head == 0) { lin[0] = px * sc; lin[1] = py * sc; lin[2] = pz * sc; }
        else { ang[0] = px * sc; ang[1] = py * sc; ang[2] = pz * sc; }
        __syncwarp();
    }
    __syncthreads();
    if (c == 0) {
        float lwx = R[0] * lin[0] + R[3] * lin[1] + R[6] * lin[2];
        float lwy = R[1] * lin[0] + R[4] * lin[1] + R[7] * lin[2];
        float lwz = R[2] * lin[0] + R[5] * lin[1] + R[8] * lin[2];
        float awx = R[0] * ang[0] + R[3] * ang[1] + R[6] * ang[2];
        float awy = R[1] * ang[0] + R[4] * ang[1] + R[7] * ang[2];
        float awz = R[2] * ang[0] + R[5] * ang[1] + R[8] * ang[2];
        float qx0 = query_x[q * 3 + 0], qx1 = query_x[q * 3 + 1], qx2 = query_x[q * 3 + 2];
        float ox = qx1 * lwz - qx2 * lwy;
        float oy = qx2 * lwx - qx0 * lwz;
        float oz = qx0 * lwy - qx1 * lwx;
        float ww = query_w[q];
        atomicAdd(&accOut[0], ww * (ox + awx));
        atomicAdd(&accOut[1], ww * (oy + awy));
        atomicAdd(&accOut[2], ww * (oz + awz));
        atomicAdd(&accOut[3], ww * lwx);
        atomicAdd(&accOut[4], ww * lwy);
        atomicAdd(&accOut[5], ww * lwz);
    }
    __syncthreads();
    if (tid < 6) {
        int tt = blockIdx.x >> 5;
        int idx = (tid < 3) ? (tt * 3 + tid) : (NT * 3 + tt * 3 + (tid - 3));
        atomicAdd(out + idx, accOut[tid]);
    }
}

extern "C" void kernel_launch(void* const* d_in, const int* in_sizes, int n_in,
                              void* d_out, int out_size) {
    const float* Ts      = (const float*)d_in[0];
    const float* time_   = (const float*)d_in[1];
    const float* query_x = (const float*)d_in[2];
    const float* query_f = (const float*)d_in[3];
    const float* query_w = (const float*)d_in[4];
    const float* kx0     = (const float*)d_in[5];
    const float* kf0     = (const float*)d_in[6];
    const float* kx1     = (const float*)d_in[7];
    const float* kf1     = (const float*)d_in[8];
    const int*   es0     = (const int*)d_in[9];
    const int*   ed0     = (const int*)d_in[10];
    const int*   es1     = (const int*)d_in[11];
    const int*   ed1     = (const int*)d_in[12];
    const float* W_qt    = (const float*)d_in[13];
    const float* b_qt    = (const float*)d_in[14];
    const float* W1_r    = (const float*)d_in[15];
    const float* b1_r    = (const float*)d_in[16];
    const float* W2_r    = (const float*)d_in[17];
    const float* b2_r    = (const float*)d_in[18];
    const float* p00     = (const float*)d_in[19];
    const float* prest   = (const float*)d_in[20];
    const float* Ws_tp   = (const float*)d_in[21];
    const float* Wv_tp   = (const float*)d_in[22];
    float* out = (float*)d_out;

    cudaFuncSetAttribute(edge_mma_kernel, cudaFuncAttributeMaxDynamicSharedMemorySize,
                         EDGE_SMEM);

    zero_kernel<<<2048, 256>>>(out);
    hist_kernel<<<1024, 256>>>(ed0, ed1);
    scan_kernel<<<1, 1024>>>();
    prep_kernel<<<NT, 128>>>(Ts, time_, query_x, W_qt, b_qt, W1_r, b1_r);
    scatter_kernel<<<512, 256>>>(es0, ed0, es1, ed1);
    edge_mma_kernel<<<2 * BPS, NTHREADS, EDGE_SMEM>>>(kx0, kf0, kx1, kf1, W1_r, W2_r, b2_r);
    tp_kernel<<<NN / 8, 256>>>(query_f, query_x, query_w, p00, prest, Ws_tp, Wv_tp, out);
}